// round 5
// baseline (speedup 1.0000x reference)
#include <cuda_runtime.h>
#include <cstddef>

// ---------------- problem constants ----------------
#define B_   8
#define CIN  512
#define EMB_ 512
#define P_   4096   // 64*64 queries
#define L_   1024   // 32*32 keys

// ---------------- scratch (no allocation allowed -> device globals) -------
__device__ float g_Wq[CIN * EMB_];                    // folded proj_in^T @ wq
__device__ float g_bq[EMB_];                          // folded bias
__device__ float g_Q[(size_t)B_ * P_ * EMB_];         // 64 MB
__device__ float g_K[(size_t)B_ * L_ * EMB_];         // 16 MB
__device__ float g_V[(size_t)B_ * L_ * EMB_];         // 16 MB
__device__ float g_S[(size_t)B_ * P_ * L_];           // 134 MB scores
__device__ float g_A[(size_t)B_ * P_ * EMB_];         // 64 MB attn out

// ---------------- generic 128x128x8 SGEMM, 8x8 per thread, double-buffered -
// A_KM:  true  -> A element = A[k*lda + m]   (reduction dim is row)
//        false -> A element = A[m*lda + k]
// B_KN:  true  -> B element = B[k*ldb + n]
//        false -> B element = B[n*ldb + k]
// BIAS:  0 none, 1 per-n, 2 per-m
// ACC:   C += result (read-modify-write)
// SCALE: multiply result by `scale`
template <bool A_KM, bool B_KN, int BIAS, bool ACC, bool SCALE>
__global__ __launch_bounds__(256) void gemm128(
    const float* __restrict__ Ag, const float* __restrict__ Bg,
    float* __restrict__ Cg, const float* __restrict__ bias, float scale,
    int M, int N, int K, int lda, int ldb, int ldc,
    size_t sA, size_t sB, size_t sC)
{
    const int bm = blockIdx.y * 128;
    const int bn = blockIdx.x * 128;
    const float* A = Ag + (size_t)blockIdx.z * sA;
    const float* B = Bg + (size_t)blockIdx.z * sB;
    float*       C = Cg + (size_t)blockIdx.z * sC;

    __shared__ __align__(16) float As[2][8][128];
    __shared__ __align__(16) float Bs[2][8][128];

    const int tid = threadIdx.x;     // 0..255
    const int tx  = tid & 15;        // n direction
    const int ty  = tid >> 4;        // m direction

    // per-thread global load coordinates
    const int arK = tid >> 5;            // A_KM:  k-row (0..7)
    const int acK = (tid & 31) * 4;      // A_KM:  m-col
    const int arM = tid >> 1;            // !A_KM: m-row (0..127)
    const int acM = (tid & 1) * 4;       // !A_KM: k-col

    float acc[8][8];
#pragma unroll
    for (int i = 0; i < 8; i++)
#pragma unroll
        for (int j = 0; j < 8; j++) acc[i][j] = 0.f;

    // ---- prologue: load tile 0 ----
    float4 va, vb;
    if (A_KM) va = *(const float4*)&A[(size_t)arK * lda + bm + acK];
    else      va = *(const float4*)&A[(size_t)(bm + arM) * lda + acM];
    if (B_KN) vb = *(const float4*)&B[(size_t)arK * ldb + bn + acK];
    else      vb = *(const float4*)&B[(size_t)(bn + arM) * ldb + acM];

    if (A_KM) { *(float4*)&As[0][arK][acK] = va; }
    else {
        As[0][acM + 0][arM] = va.x; As[0][acM + 1][arM] = va.y;
        As[0][acM + 2][arM] = va.z; As[0][acM + 3][arM] = va.w;
    }
    if (B_KN) { *(float4*)&Bs[0][arK][acK] = vb; }
    else {
        Bs[0][acM + 0][arM] = vb.x; Bs[0][acM + 1][arM] = vb.y;
        Bs[0][acM + 2][arM] = vb.z; Bs[0][acM + 3][arM] = vb.w;
    }
    __syncthreads();

    const int KT = K >> 3;
    int buf = 0;
    for (int kt = 0; kt < KT; kt++) {
        // ---- prefetch next tile into registers (overlaps with compute) ----
        if (kt + 1 < KT) {
            const int k0 = (kt + 1) << 3;
            if (A_KM) va = *(const float4*)&A[(size_t)(k0 + arK) * lda + bm + acK];
            else      va = *(const float4*)&A[(size_t)(bm + arM) * lda + k0 + acM];
            if (B_KN) vb = *(const float4*)&B[(size_t)(k0 + arK) * ldb + bn + acK];
            else      vb = *(const float4*)&B[(size_t)(bn + arM) * ldb + k0 + acM];
        }

        // ---- compute current tile ----
#pragma unroll
        for (int k = 0; k < 8; k++) {
            float a[8], b[8];
            *(float4*)&a[0] = *(const float4*)&As[buf][k][ty * 8];
            *(float4*)&a[4] = *(const float4*)&As[buf][k][ty * 8 + 4];
            *(float4*)&b[0] = *(const float4*)&Bs[buf][k][tx * 8];
            *(float4*)&b[4] = *(const float4*)&Bs[buf][k][tx * 8 + 4];
#pragma unroll
            for (int i = 0; i < 8; i++)
#pragma unroll
                for (int j = 0; j < 8; j++) acc[i][j] += a[i] * b[j];
        }

        // ---- commit next tile to the other buffer ----
        if (kt + 1 < KT) {
            buf ^= 1;
            if (A_KM) { *(float4*)&As[buf][arK][acK] = va; }
            else {
                As[buf][acM + 0][arM] = va.x; As[buf][acM + 1][arM] = va.y;
                As[buf][acM + 2][arM] = va.z; As[buf][acM + 3][arM] = va.w;
            }
            if (B_KN) { *(float4*)&Bs[buf][arK][acK] = vb; }
            else {
                Bs[buf][acM + 0][arM] = vb.x; Bs[buf][acM + 1][arM] = vb.y;
                Bs[buf][acM + 2][arM] = vb.z; Bs[buf][acM + 3][arM] = vb.w;
            }
            __syncthreads();
        }
    }

    // ---- epilogue ----
#pragma unroll
    for (int i = 0; i < 8; i++) {
        int m = bm + ty * 8 + i;
#pragma unroll
        for (int j = 0; j < 8; j += 4) {
            int n = bn + tx * 8 + j;
            float4 v;
            v.x = acc[i][j]; v.y = acc[i][j + 1];
            v.z = acc[i][j + 2]; v.w = acc[i][j + 3];
            if (SCALE) { v.x *= scale; v.y *= scale; v.z *= scale; v.w *= scale; }
            if (BIAS == 1) {
                float4 bb = *(const float4*)&bias[n];
                v.x += bb.x; v.y += bb.y; v.z += bb.z; v.w += bb.w;
            } else if (BIAS == 2) {
                float bv = bias[m];
                v.x += bv; v.y += bv; v.z += bv; v.w += bv;
            }
            float* cp = &C[(size_t)m * ldc + n];
            if (ACC) {
                float4 o = *(const float4*)cp;
                v.x += o.x; v.y += o.y; v.z += o.z; v.w += o.w;
            }
            *(float4*)cp = v;
        }
    }
}

// ---------------- folded bias: bq'[e] = proj_in_b @ wq + wq_b --------------
__global__ void fold_bias(const float* __restrict__ pib,
                          const float* __restrict__ wq,
                          const float* __restrict__ wqb,
                          float* __restrict__ out)
{
    int e = threadIdx.x;  // 512 threads
    float s = wqb[e];
    for (int f = 0; f < EMB_; f++) s += pib[f] * wq[f * EMB_ + e];
    out[e] = s;
}

// ---------------- row softmax over L_=1024 (one block per row) -------------
__global__ __launch_bounds__(256) void softmax_rows(float* __restrict__ S)
{
    size_t row = blockIdx.x;
    float4* p = (float4*)(S + row * (size_t)L_);
    int t = threadIdx.x;                     // 256 threads * float4 = 1024
    float4 v = p[t];

    __shared__ float red[8];
    // max
    float m = fmaxf(fmaxf(v.x, v.y), fmaxf(v.z, v.w));
#pragma unroll
    for (int o = 16; o > 0; o >>= 1) m = fmaxf(m, __shfl_xor_sync(0xffffffffu, m, o));
    if ((t & 31) == 0) red[t >> 5] = m;
    __syncthreads();
    if (t == 0) {
        float mm = red[0];
#pragma unroll
        for (int i = 1; i < 8; i++) mm = fmaxf(mm, red[i]);
        red[0] = mm;
    }
    __syncthreads();
    m = red[0];
    __syncthreads();

    v.x = __expf(v.x - m); v.y = __expf(v.y - m);
    v.z = __expf(v.z - m); v.w = __expf(v.w - m);
    float s = v.x + v.y + v.z + v.w;
#pragma unroll
    for (int o = 16; o > 0; o >>= 1) s += __shfl_xor_sync(0xffffffffu, s, o);
    if ((t & 31) == 0) red[t >> 5] = s;
    __syncthreads();
    if (t == 0) {
        float tot = 0.f;
#pragma unroll
        for (int i = 0; i < 8; i++) tot += red[i];
        red[0] = tot;
    }
    __syncthreads();
    float inv = 1.0f / red[0];
    v.x *= inv; v.y *= inv; v.z *= inv; v.w *= inv;
    p[t] = v;
}

// ---------------- launch ---------------------------------------------------
extern "C" void kernel_launch(void* const* d_in, const int* in_sizes, int n_in,
                              void* d_out, int out_size)
{
    const float* input   = (const float*)d_in[0];   // [8,512,64,64]
    const float* context = (const float*)d_in[1];   // [8,512,32,32]
    const float* piw     = (const float*)d_in[2];   // [512(f),512(c)]
    const float* pib     = (const float*)d_in[3];
    const float* wq      = (const float*)d_in[4];   // [512(f),512(e)]
    const float* wqb     = (const float*)d_in[5];
    const float* wk      = (const float*)d_in[6];
    const float* wkb     = (const float*)d_in[7];
    const float* wv      = (const float*)d_in[8];
    const float* wvb     = (const float*)d_in[9];
    const float* pow_    = (const float*)d_in[10];  // [512(o),1024(c|e)]
    const float* pob     = (const float*)d_in[11];
    float* out = (float*)d_out;                     // [8,512,64,64]

    float *Wq, *bq, *Q, *K, *V, *S, *A;
    cudaGetSymbolAddress((void**)&Wq, g_Wq);
    cudaGetSymbolAddress((void**)&bq, g_bq);
    cudaGetSymbolAddress((void**)&Q,  g_Q);
    cudaGetSymbolAddress((void**)&K,  g_K);
    cudaGetSymbolAddress((void**)&V,  g_V);
    cudaGetSymbolAddress((void**)&S,  g_S);
    cudaGetSymbolAddress((void**)&A,  g_A);

    const float att_scale = 0.044194173824159216f;  // 512^-0.5

    // 1) fold weights: Wq'[c][e] = sum_f piw[f][c] * wq[f][e]
    gemm128<true, true, 0, false, false><<<dim3(4, 4, 1), 256>>>(
        piw, wq, Wq, nullptr, 1.f, 512, 512, 512, 512, 512, 512, 0, 0, 0);
    fold_bias<<<1, 512>>>(pib, wq, wqb, bq);

    // 2) Q[b][p][e] = sum_c input[b][c][p] * Wq'[c][e] + bq'
    gemm128<true, true, 1, false, false><<<dim3(4, 32, B_), 256>>>(
        input, Wq, Q, bq, 1.f, P_, EMB_, CIN, P_, EMB_, EMB_,
        (size_t)CIN * P_, 0, (size_t)P_ * EMB_);

    // 3) K / V : [b][l][e] = sum_c ctx[b][c][l] * w[c][e] + b
    gemm128<true, true, 1, false, false><<<dim3(4, 8, B_), 256>>>(
        context, wk, K, wkb, 1.f, L_, EMB_, CIN, L_, EMB_, EMB_,
        (size_t)CIN * L_, 0, (size_t)L_ * EMB_);
    gemm128<true, true, 1, false, false><<<dim3(4, 8, B_), 256>>>(
        context, wv, V, wvb, 1.f, L_, EMB_, CIN, L_, EMB_, EMB_,
        (size_t)CIN * L_, 0, (size_t)L_ * EMB_);

    // 4) S[b][p][l] = scale * sum_e Q[p][e] * K[l][e]
    gemm128<false, false, 0, false, true><<<dim3(8, 32, B_), 256>>>(
        Q, K, S, nullptr, att_scale, P_, L_, EMB_, EMB_, EMB_, L_,
        (size_t)P_ * EMB_, (size_t)L_ * EMB_, (size_t)P_ * L_);

    // 5) softmax over L
    softmax_rows<<<B_ * P_, 256>>>(S);

    // 6) A[b][p][e] = sum_l S[p][l] * V[l][e]
    gemm128<false, true, 0, false, false><<<dim3(4, 32, B_), 256>>>(
        S, V, A, nullptr, 1.f, P_, EMB_, L_, L_, EMB_, EMB_,
        (size_t)P_ * L_, (size_t)L_ * EMB_, (size_t)P_ * EMB_);

    // 7) out[b][o][p] = sum_c Wo1[o][c]*input[c][p] + pob[o]   (first half)
    gemm128<false, true, 2, false, false><<<dim3(32, 4, B_), 256>>>(
        pow_, input, out, pob, 1.f, CIN, P_, CIN, EMB_ + CIN, P_, P_,
        0, (size_t)CIN * P_, (size_t)CIN * P_);

    // 8) out[b][o][p] += sum_e Wo2[o][e]*A[p][e]               (second half)
    gemm128<false, false, 0, true, false><<<dim3(32, 4, B_), 256>>>(
        pow_ + CIN, A, out, nullptr, 1.f, CIN, P_, EMB_, EMB_ + CIN, EMB_, P_,
        0, (size_t)P_ * EMB_, (size_t)CIN * P_);
}

// round 7
// speedup vs baseline: 1.2050x; 1.2050x over previous
#include <cuda_runtime.h>
#include <cstdint>
#include <cstddef>

// ---------------- problem constants ----------------
#define B_   8
#define CIN  512
#define EMB_ 512
#define P_   4096   // 64*64 queries
#define L_   1024   // 32*32 keys

// ---------------- scratch (no allocation allowed -> device globals) -------
__device__ float g_Wq[CIN * EMB_];
__device__ float g_bq[EMB_];
__device__ float g_Q[(size_t)B_ * P_ * EMB_];
__device__ float g_K[(size_t)B_ * L_ * EMB_];
__device__ float g_V[(size_t)B_ * L_ * EMB_];
__device__ float g_S[(size_t)B_ * P_ * L_];
__device__ float g_A[(size_t)B_ * P_ * EMB_];

// ---------------- tf32 helpers ---------------------------------------------
__device__ __forceinline__ uint32_t f2tf(float x) {
    uint32_t r;
    asm("cvt.rna.tf32.f32 %0, %1;" : "=r"(r) : "f"(x));
    return r;
}
__device__ __forceinline__ void split_tf32(float x, uint32_t& hi, uint32_t& lo) {
    hi = f2tf(x);
    float l = x - __uint_as_float(hi);
    lo = f2tf(l);
}
__device__ __forceinline__ void mma_tf32(float* d, const uint32_t* a, const uint32_t* b) {
    asm volatile(
        "mma.sync.aligned.m16n8k8.row.col.f32.tf32.tf32.f32 "
        "{%0,%1,%2,%3}, {%4,%5,%6,%7}, {%8,%9}, {%0,%1,%2,%3};"
        : "+f"(d[0]), "+f"(d[1]), "+f"(d[2]), "+f"(d[3])
        : "r"(a[0]), "r"(a[1]), "r"(a[2]), "r"(a[3]), "r"(b[0]), "r"(b[1]));
}

// ---------------- 3xTF32 tensor-core GEMM ----------------------------------
// CTA tile 128(m) x 64(n), K-chunk 16, double-buffered smem with XOR swizzle.
// 8 warps as 4(m) x 2(n); warp tile 32x32 = 2 x 4 m16n8k8 tiles; 3 mma passes.
// A_KM:  true -> A[k*lda + m], false -> A[m*lda + k]
// B_KN:  true -> B[k*ldb + n], false -> B[n*ldb + k]
// BIAS:  0 none, 1 per-n, 2 per-m;  ACC: C += ;  SCALE: multiply by scale
template <bool A_KM, bool B_KN, int BIAS, bool ACC, bool SCALE>
__global__ __launch_bounds__(256, 2) void gemm_tc(
    const float* __restrict__ Ag, const float* __restrict__ Bg,
    float* __restrict__ Cg, const float* __restrict__ bias, float scale,
    int M, int N, int K, int lda, int ldb, int ldc,
    size_t sA, size_t sB, size_t sC)
{
    const int bm = blockIdx.y * 128;
    const int bn = blockIdx.x * 64;
    const float* A = Ag + (size_t)blockIdx.z * sA;
    const float* B = Bg + (size_t)blockIdx.z * sB;
    float*       C = Cg + (size_t)blockIdx.z * sC;

    __shared__ __align__(16) float As[2][16 * 128];
    __shared__ __align__(16) float Bs[2][16 * 64];

    const int tid  = threadIdx.x;
    const int lane = tid & 31;
    const int wid  = tid >> 5;
    const int g    = lane >> 2;      // group id 0..7
    const int tig  = lane & 3;       // thread-in-group 0..3
    const int m_warp = (wid >> 1) * 32;   // 4 warps along m
    const int n_warp = (wid & 1) * 32;    // 2 warps along n

    float acc[2][4][4];
#pragma unroll
    for (int i = 0; i < 2; i++)
#pragma unroll
        for (int j = 0; j < 4; j++)
#pragma unroll
            for (int r = 0; r < 4; r++) acc[i][j][r] = 0.f;

    // ---- global-load / smem-store helpers (element (k,m) -> col m^((k&3)<<3))
    float4 pa[2], pb;
    auto loadA = [&](int k0) {
        if (A_KM) {
            int k = tid >> 5, c = (tid & 31) * 4;
            pa[0] = *(const float4*)&A[(size_t)(k0 + k) * lda + bm + c];
            pa[1] = *(const float4*)&A[(size_t)(k0 + k + 8) * lda + bm + c];
        } else {
            int r = tid & 127, kh = (tid >> 7) * 8;
            pa[0] = *(const float4*)&A[(size_t)(bm + r) * lda + k0 + kh];
            pa[1] = *(const float4*)&A[(size_t)(bm + r) * lda + k0 + kh + 4];
        }
    };
    auto storeA = [&](int buf) {
        if (A_KM) {
            int k = tid >> 5, c = (tid & 31) * 4;
#pragma unroll
            for (int p = 0; p < 2; p++) {
                int kk = k + 8 * p;
                *(float4*)&As[buf][kk * 128 + (c ^ ((kk & 3) << 3))] = pa[p];
            }
        } else {
            int r = tid & 127, kh = (tid >> 7) * 8;
            const float* v = (const float*)pa;   // 8 consecutive k values
#pragma unroll
            for (int q = 0; q < 8; q++) {
                int kk = kh + q;
                As[buf][kk * 128 + (r ^ ((kk & 3) << 3))] = v[q];
            }
        }
    };
    auto loadB = [&](int k0) {
        if (B_KN) {
            int k = tid >> 4, c = (tid & 15) * 4;
            pb = *(const float4*)&B[(size_t)(k0 + k) * ldb + bn + c];
        } else {
            int r = tid & 63, k4 = (tid >> 6) * 4;
            pb = *(const float4*)&B[(size_t)(bn + r) * ldb + k0 + k4];
        }
    };
    auto storeB = [&](int buf) {
        if (B_KN) {
            int k = tid >> 4, c = (tid & 15) * 4;
            *(float4*)&Bs[buf][k * 64 + (c ^ ((k & 3) << 3))] = pb;
        } else {
            int r = tid & 63, k4 = (tid >> 6) * 4;
            const float* v = (const float*)&pb;
#pragma unroll
            for (int q = 0; q < 4; q++) {
                int kk = k4 + q;
                Bs[buf][kk * 64 + (r ^ ((kk & 3) << 3))] = v[q];
            }
        }
    };

    // ---- prologue ----
    loadA(0); loadB(0);
    storeA(0); storeB(0);
    __syncthreads();

    const int KT = K >> 4;
    int buf = 0;
    const int sw = tig << 3;   // frag-load swizzle (k&3 == tig for both k rows)

    for (int kt = 0; kt < KT; kt++) {
        if (kt + 1 < KT) { loadA((kt + 1) << 4); loadB((kt + 1) << 4); }

#pragma unroll
        for (int ks = 0; ks < 16; ks += 8) {
            const float* Sa = &As[buf][0];
            const float* Sb = &Bs[buf][0];
            const int kr0 = (ks + tig) * 64;        // B row offsets
            const int kr1 = (ks + tig + 4) * 64;

            // B fragments (hi/lo), shared across the 2 m-tiles
            uint32_t bhi[4][2], blo[4][2];
#pragma unroll
            for (int j = 0; j < 4; j++) {
                int nb = n_warp + j * 8;
                float b0 = Sb[kr0 + ((nb + g) ^ sw)];
                float b1 = Sb[kr1 + ((nb + g) ^ sw)];
                split_tf32(b0, bhi[j][0], blo[j][0]);
                split_tf32(b1, bhi[j][1], blo[j][1]);
            }
#pragma unroll
            for (int i = 0; i < 2; i++) {
                int ma = m_warp + i * 16;
                float a0 = Sa[(ks + tig) * 128 + ((ma + g) ^ sw)];
                float a1 = Sa[(ks + tig) * 128 + ((ma + g + 8) ^ sw)];
                float a2 = Sa[(ks + tig + 4) * 128 + ((ma + g) ^ sw)];
                float a3 = Sa[(ks + tig + 4) * 128 + ((ma + g + 8) ^ sw)];
                uint32_t ahi[4], alo[4];
                split_tf32(a0, ahi[0], alo[0]);
                split_tf32(a1, ahi[1], alo[1]);
                split_tf32(a2, ahi[2], alo[2]);
                split_tf32(a3, ahi[3], alo[3]);
#pragma unroll
                for (int j = 0; j < 4; j++) {
                    mma_tf32(acc[i][j], ahi, bhi[j]);   // hi*hi
                    mma_tf32(acc[i][j], ahi, blo[j]);   // hi*lo
                    mma_tf32(acc[i][j], alo, bhi[j]);   // lo*hi
                }
            }
        }

        if (kt + 1 < KT) {
            buf ^= 1;
            storeA(buf); storeB(buf);
            __syncthreads();
        }
    }

    // ---- epilogue: thread owns (g, 2*tig) pattern of each 16x8 tile ----
#pragma unroll
    for (int i = 0; i < 2; i++) {
#pragma unroll
        for (int j = 0; j < 4; j++) {
            int m0 = bm + m_warp + i * 16 + g;
            int n0 = bn + n_warp + j * 8 + tig * 2;
#pragma unroll
            for (int h = 0; h < 2; h++) {           // h=0: row m0, h=1: row m0+8
                int m = m0 + h * 8;
                float2 v;
                v.x = acc[i][j][h * 2 + 0];
                v.y = acc[i][j][h * 2 + 1];
                if (SCALE) { v.x *= scale; v.y *= scale; }
                if (BIAS == 1) {
                    float2 bb = *(const float2*)&bias[n0];
                    v.x += bb.x; v.y += bb.y;
                } else if (BIAS == 2) {
                    float bv = bias[m];
                    v.x += bv; v.y += bv;
                }
                float* cp = &C[(size_t)m * ldc + n0];
                if (ACC) {
                    float2 o = *(const float2*)cp;
                    v.x += o.x; v.y += o.y;
                }
                *(float2*)cp = v;
            }
        }
    }
}

// ---------------- folded bias: bq'[e] = proj_in_b @ wq + wq_b --------------
__global__ void fold_bias(const float* __restrict__ pib,
                          const float* __restrict__ wq,
                          const float* __restrict__ wqb,
                          float* __restrict__ out)
{
    int e = threadIdx.x;  // 512 threads
    float s = wqb[e];
    for (int f = 0; f < EMB_; f++) s += pib[f] * wq[f * EMB_ + e];
    out[e] = s;
}

// ---------------- row softmax over L_=1024 (one block per row) -------------
__global__ __launch_bounds__(256) void softmax_rows(float* __restrict__ S)
{
    size_t row = blockIdx.x;
    float4* p = (float4*)(S + row * (size_t)L_);
    int t = threadIdx.x;
    float4 v = p[t];

    __shared__ float red[8];
    float m = fmaxf(fmaxf(v.x, v.y), fmaxf(v.z, v.w));
#pragma unroll
    for (int o = 16; o > 0; o >>= 1) m = fmaxf(m, __shfl_xor_sync(0xffffffffu, m, o));
    if ((t & 31) == 0) red[t >> 5] = m;
    __syncthreads();
    if (t == 0) {
        float mm = red[0];
#pragma unroll
        for (int i = 1; i < 8; i++) mm = fmaxf(mm, red[i]);
        red[0] = mm;
    }
    __syncthreads();
    m = red[0];
    __syncthreads();

    v.x = __expf(v.x - m); v.y = __expf(v.y - m);
    v.z = __expf(v.z - m); v.w = __expf(v.w - m);
    float s = v.x + v.y + v.z + v.w;
#pragma unroll
    for (int o = 16; o > 0; o >>= 1) s += __shfl_xor_sync(0xffffffffu, s, o);
    if ((t & 31) == 0) red[t >> 5] = s;
    __syncthreads();
    if (t == 0) {
        float tot = 0.f;
#pragma unroll
        for (int i = 0; i < 8; i++) tot += red[i];
        red[0] = tot;
    }
    __syncthreads();
    float inv = 1.0f / red[0];
    v.x *= inv; v.y *= inv; v.z *= inv; v.w *= inv;
    p[t] = v;
}

// ---------------- launch ---------------------------------------------------
extern "C" void kernel_launch(void* const* d_in, const int* in_sizes, int n_in,
                              void* d_out, int out_size)
{
    const float* input   = (const float*)d_in[0];   // [8,512,64,64]
    const float* context = (const float*)d_in[1];   // [8,512,32,32]
    const float* piw     = (const float*)d_in[2];   // [512(f),512(c)]
    const float* pib     = (const float*)d_in[3];
    const float* wq      = (const float*)d_in[4];   // [512(f),512(e)]
    const float* wqb     = (const float*)d_in[5];
    const float* wk      = (const float*)d_in[6];
    const float* wkb     = (const float*)d_in[7];
    const float* wv      = (const float*)d_in[8];
    const float* wvb     = (const float*)d_in[9];
    const float* pow_    = (const float*)d_in[10];  // [512(o),1024(c|e)]
    const float* pob     = (const float*)d_in[11];
    float* out = (float*)d_out;                     // [8,512,64,64]

    float *Wq, *bq, *Q, *K, *V, *S, *A;
    cudaGetSymbolAddress((void**)&Wq, g_Wq);
    cudaGetSymbolAddress((void**)&bq, g_bq);
    cudaGetSymbolAddress((void**)&Q,  g_Q);
    cudaGetSymbolAddress((void**)&K,  g_K);
    cudaGetSymbolAddress((void**)&V,  g_V);
    cudaGetSymbolAddress((void**)&S,  g_S);
    cudaGetSymbolAddress((void**)&A,  g_A);

    const float att_scale = 0.044194173824159216f;  // 512^-0.5

    // 1) fold weights: Wq'[c][e] = sum_f piw[f][c] * wq[f][e]
    gemm_tc<true, true, 0, false, false><<<dim3(8, 4, 1), 256>>>(
        piw, wq, Wq, nullptr, 1.f, 512, 512, 512, 512, 512, 512, 0, 0, 0);
    fold_bias<<<1, 512>>>(pib, wq, wqb, bq);

    // 2) Q[b][p][e] = sum_c input[b][c][p] * Wq'[c][e] + bq'
    gemm_tc<true, true, 1, false, false><<<dim3(8, 32, B_), 256>>>(
        input, Wq, Q, bq, 1.f, P_, EMB_, CIN, P_, EMB_, EMB_,
        (size_t)CIN * P_, 0, (size_t)P_ * EMB_);

    // 3) K / V : [b][l][e] = sum_c ctx[b][c][l] * w[c][e] + b
    gemm_tc<true, true, 1, false, false><<<dim3(8, 8, B_), 256>>>(
        context, wk, K, wkb, 1.f, L_, EMB_, CIN, L_, EMB_, EMB_,
        (size_t)CIN * L_, 0, (size_t)L_ * EMB_);
    gemm_tc<true, true, 1, false, false><<<dim3(8, 8, B_), 256>>>(
        context, wv, V, wvb, 1.f, L_, EMB_, CIN, L_, EMB_, EMB_,
        (size_t)CIN * L_, 0, (size_t)L_ * EMB_);

    // 4) S[b][p][l] = scale * sum_e Q[p][e] * K[l][e]
    gemm_tc<false, false, 0, false, true><<<dim3(16, 32, B_), 256>>>(
        Q, K, S, nullptr, att_scale, P_, L_, EMB_, EMB_, EMB_, L_,
        (size_t)P_ * EMB_, (size_t)L_ * EMB_, (size_t)P_ * L_);

    // 5) softmax over L
    softmax_rows<<<B_ * P_, 256>>>(S);

    // 6) A[b][p][e] = sum_l S[p][l] * V[l][e]
    gemm_tc<false, true, 0, false, false><<<dim3(8, 32, B_), 256>>>(
        S, V, A, nullptr, 1.f, P_, EMB_, L_, L_, EMB_, EMB_,
        (size_t)P_ * L_, (size_t)L_ * EMB_, (size_t)P_ * EMB_);

    // 7) out[b][o][p] = sum_c Wo1[o][c]*input[c][p] + pob[o]   (first half)
    gemm_tc<false, true, 2, false, false><<<dim3(64, 4, B_), 256>>>(
        pow_, input, out, pob, 1.f, CIN, P_, CIN, EMB_ + CIN, P_, P_,
        0, (size_t)CIN * P_, (size_t)CIN * P_);

    // 8) out[b][o][p] += sum_e Wo2[o][e]*A[p][e]               (second half)
    gemm_tc<false, false, 0, true, false><<<dim3(64, 4, B_), 256>>>(
        pow_ + CIN, A, out, nullptr, 1.f, CIN, P_, EMB_, EMB_ + CIN, EMB_, P_,
        0, (size_t)P_ * EMB_, (size_t)CIN * P_);
}